// round 11
// baseline (speedup 1.0000x reference)
#include <cuda_runtime.h>
#include <cuda_fp16.h>
#include <cstdint>

#define OMEGA0 30.0f
#define BLK 128
#define MAXCTAS 740   // 148 SMs x 5 CTAs

// ---------------- packed f32x2 ops (sm_103a FFMA2 path) ----------------
union F2U { unsigned long long u; float2 f; uint2 i; };

__device__ __forceinline__ float2 ffma2(float2 a, float2 b, float2 c) {
    F2U A, B, C, D; A.f = a; B.f = b; C.f = c;
    asm("fma.rn.f32x2 %0, %1, %2, %3;" : "=l"(D.u) : "l"(A.u), "l"(B.u), "l"(C.u));
    return D.f;
}
__device__ __forceinline__ float2 fmul2(float2 a, float2 b) {
    F2U A, B, D; A.f = a; B.f = b;
    asm("mul.rn.f32x2 %0, %1, %2;" : "=l"(D.u) : "l"(A.u), "l"(B.u));
    return D.f;
}
__device__ __forceinline__ float2 fadd2(float2 a, float2 b) {
    F2U A, B, D; A.f = a; B.f = b;
    asm("add.rn.f32x2 %0, %1, %2;" : "=l"(D.u) : "l"(A.u), "l"(B.u));
    return D.f;
}
__device__ __forceinline__ float2 mk2(float v) { return make_float2(v, v); }

// two sines on the fma pipe: reduce by pi (parity sign), deg-9 odd Taylor
__device__ __forceinline__ float2 sin2_poly(float2 t) {
    const float MAGIC = 12582912.0f;   // 1.5 * 2^23
    F2U u;
    u.f = ffma2(t, mk2(0.3183098861837907f), mk2(MAGIC));   // k + MAGIC (int in mantissa)
    uint32_t s0 = u.i.x << 31, s1 = u.i.y << 31;            // parity(k) -> sign bit
    float2 k = fadd2(u.f, mk2(-MAGIC));
    float2 r = ffma2(k, mk2(-3.14159274101257324f), t);     // t - k*pi_hi
    r = ffma2(k, mk2(8.742277657347586e-8f), r);            // - k*pi_lo
    float2 r2 = fmul2(r, r);
    float2 p = ffma2(r2, mk2(2.75573192e-6f), mk2(-1.98412698e-4f));
    p = ffma2(r2, p, mk2(8.33333333e-3f));
    p = ffma2(r2, p, mk2(-0.16666666666f));
    float2 q = fmul2(r, r2);
    F2U res; res.f = ffma2(q, p, r);                         // r + r^3 * p
    res.i.x ^= s0; res.i.y ^= s1;                            // (-1)^k
    return res.f;
}

// ---------------- misc helpers ----------------
__device__ __forceinline__ float fast_sigmoid(float t) {
    return __fdividef(1.0f, 1.0f + __expf(-t));
}
__device__ __forceinline__ uint32_t pack_f16x2(float x, float y) {
    uint32_t r;
    asm("cvt.rn.f16x2.f32 %0, %1, %2;" : "=r"(r) : "f"(y), "f"(x));
    return r;
}
// D += A * B
__device__ __forceinline__ void mma_f16(float d[4], const uint32_t a[4],
                                        uint32_t b0, uint32_t b1) {
    asm volatile(
        "mma.sync.aligned.m16n8k16.row.col.f32.f16.f16.f32 "
        "{%0,%1,%2,%3}, {%4,%5,%6,%7}, {%8,%9}, {%0,%1,%2,%3};"
        : "+f"(d[0]), "+f"(d[1]), "+f"(d[2]), "+f"(d[3])
        : "r"(a[0]), "r"(a[1]), "r"(a[2]), "r"(a[3]), "r"(b0), "r"(b1));
}
// D = A * B + {c0,c1,c0,c1}
__device__ __forceinline__ void mma_f16_bias(float d[4], const uint32_t a[4],
                                             uint32_t b0, uint32_t b1,
                                             float c0, float c1) {
    asm volatile(
        "mma.sync.aligned.m16n8k16.row.col.f32.f16.f16.f32 "
        "{%0,%1,%2,%3}, {%4,%5,%6,%7}, {%8,%9}, {%10,%11,%10,%11};"
        : "=f"(d[0]), "=f"(d[1]), "=f"(d[2]), "=f"(d[3])
        : "r"(a[0]), "r"(a[1]), "r"(a[2]), "r"(a[3]), "r"(b0), "r"(b1),
          "f"(c0), "f"(c1));
}

// Build A fragments (f16) for k=32 from 4 n-tiles of fp32 values in D layout.
#define BUILD_A(vsrc, Ah) do {                                                  \
    _Pragma("unroll")                                                           \
    for (int mt_ = 0; mt_ < 2; mt_++) {                                         \
        _Pragma("unroll")                                                       \
        for (int kt_ = 0; kt_ < 2; kt_++) {                                     \
            Ah[mt_][kt_][0] = pack_f16x2(vsrc[mt_][2*kt_][0],   vsrc[mt_][2*kt_][1]);   \
            Ah[mt_][kt_][1] = pack_f16x2(vsrc[mt_][2*kt_][2],   vsrc[mt_][2*kt_][3]);   \
            Ah[mt_][kt_][2] = pack_f16x2(vsrc[mt_][2*kt_+1][0], vsrc[mt_][2*kt_+1][1]); \
            Ah[mt_][kt_][3] = pack_f16x2(vsrc[mt_][2*kt_+1][2], vsrc[mt_][2*kt_+1][3]); \
        }                                                                       \
    }                                                                           \
} while (0)

__global__ void __launch_bounds__(BLK, 5)
siren_hmma(const float* __restrict__ coords,
           const float* __restrict__ w0g, const float* __restrict__ b0g,
           const float* __restrict__ w1g, const float* __restrict__ b1g,
           const float* __restrict__ w2g, const float* __restrict__ b2g,
           const float* __restrict__ w3g, const float* __restrict__ b3g,
           const float* __restrict__ w4g, const float* __restrict__ b4g,
           const float* __restrict__ w5g, const float* __restrict__ b5g,
           const float* __restrict__ wfg, const float* __restrict__ bfg,
           float* __restrict__ out, int numPts, int numTiles)
{
    __shared__ __align__(16) uint32_t fragMid[4][32][20];
    __shared__ __align__(16) uint32_t frag5[32][12];
    __shared__ float2 biasM[4][16];
    __shared__ float2 bias5[8];
    __shared__ float s_w0[64], s_b0[32], s_wf[48], s_bf[3];

    const int tid = threadIdx.x;
    const int lane = tid & 31, wid = tid >> 5;
    const int t4 = lane & 3, g = lane >> 2;

    // ---- fill weight fragments ----
#define FILL_MID(Lc, WP)                                                       \
    for (int e = tid; e < 512; e += BLK) {                                     \
        int q = e >> 5, ln = e & 31;                                           \
        int tt = ln & 3, gg = ln >> 2;                                         \
        int kt = q >> 3, r = (q >> 2) & 1, nt = q & 3;                         \
        int k0 = kt * 16 + r * 8 + tt * 2;                                     \
        int n  = nt * 8 + gg;                                                  \
        fragMid[Lc][ln][q] = pack_f16x2(OMEGA0 * WP[n * 32 + k0],              \
                                        OMEGA0 * WP[n * 32 + k0 + 1]);         \
    }
    FILL_MID(0, w1g) FILL_MID(1, w2g) FILL_MID(2, w3g) FILL_MID(3, w4g)
#undef FILL_MID

    for (int e = tid; e < 256; e += BLK) {
        int q = e >> 5, ln = e & 31;
        int tt = ln & 3, gg = ln >> 2;
        int kt = q >> 2, r = (q >> 1) & 1, nt = q & 1;
        int k0 = kt * 16 + r * 8 + tt * 2;
        int n  = nt * 8 + gg;
        frag5[ln][q] = pack_f16x2(OMEGA0 * w5g[n * 32 + k0],
                                  OMEGA0 * w5g[n * 32 + k0 + 1]);
    }
#define FILL_BIAS(Lc, BP)                                                      \
    if (tid < 16) {                                                            \
        int nt = tid >> 2, tt = tid & 3;                                       \
        biasM[Lc][tid] = make_float2(OMEGA0 * BP[nt * 8 + tt * 2],             \
                                     OMEGA0 * BP[nt * 8 + tt * 2 + 1]);        \
    }
    FILL_BIAS(0, b1g) FILL_BIAS(1, b2g) FILL_BIAS(2, b3g) FILL_BIAS(3, b4g)
#undef FILL_BIAS
    if (tid < 8) {
        int nt = tid >> 2, tt = tid & 3;
        bias5[tid] = make_float2(OMEGA0 * b5g[nt * 8 + tt * 2],
                                 OMEGA0 * b5g[nt * 8 + tt * 2 + 1]);
    }
    if (tid < 64) s_w0[tid] = OMEGA0 * w0g[tid];
    if (tid < 32) s_b0[tid] = OMEGA0 * b0g[tid];
    if (tid < 48) s_wf[tid] = wfg[tid];
    if (tid < 3)  s_bf[tid] = bfg[tid];
    __syncthreads();

    // ---------------- main loop: 128 points per CTA-iter (32 per warp) ----------------
#pragma unroll 1
    for (int tile = blockIdx.x; tile < numTiles; tile += gridDim.x) {
        const int pbase = tile * 128 + wid * 32;

        float v[2][4][4];

        // ---- layer 0: 2 -> 32 (MUFU sines) ----
#pragma unroll
        for (int mt = 0; mt < 2; mt++) {
            int p0 = pbase + mt * 16 + g;
            float2 c0 = (p0 < numPts)     ? ((const float2*)coords)[p0]     : make_float2(0.f, 0.f);
            float2 c1 = (p0 + 8 < numPts) ? ((const float2*)coords)[p0 + 8] : make_float2(0.f, 0.f);
#pragma unroll
            for (int nt = 0; nt < 4; nt++) {
                int col = nt * 8 + t4 * 2;
                float2 wa = ((const float2*)s_w0)[col];
                float2 wb = ((const float2*)s_w0)[col + 1];
                float ba = s_b0[col], bb_ = s_b0[col + 1];
                v[mt][nt][0] = __sinf(fmaf(c0.x, wa.x, fmaf(c0.y, wa.y, ba)));
                v[mt][nt][1] = __sinf(fmaf(c0.x, wb.x, fmaf(c0.y, wb.y, bb_)));
                v[mt][nt][2] = __sinf(fmaf(c1.x, wa.x, fmaf(c1.y, wa.y, ba)));
                v[mt][nt][3] = __sinf(fmaf(c1.x, wb.x, fmaf(c1.y, wb.y, bb_)));
            }
        }

        // ---- 4 middle layers 32 -> 32 on HMMA ----
#pragma unroll 1
        for (int L = 0; L < 4; L++) {
            uint32_t Ah[2][2][4];
            BUILD_A(v, Ah);

            uint32_t B[16];
            {
                const uint4* bp = (const uint4*)&fragMid[L][lane][0];
                uint4 b0_ = bp[0], b1_ = bp[1], b2_ = bp[2], b3_ = bp[3];
                B[0]=b0_.x; B[1]=b0_.y; B[2]=b0_.z; B[3]=b0_.w;
                B[4]=b1_.x; B[5]=b1_.y; B[6]=b1_.z; B[7]=b1_.w;
                B[8]=b2_.x; B[9]=b2_.y; B[10]=b2_.z; B[11]=b2_.w;
                B[12]=b3_.x; B[13]=b3_.y; B[14]=b3_.z; B[15]=b3_.w;
            }
#pragma unroll
            for (int nt = 0; nt < 4; nt++) {
                float2 bb = biasM[L][nt * 4 + t4];
#pragma unroll
                for (int mt = 0; mt < 2; mt++) {
                    mma_f16_bias(v[mt][nt], Ah[mt][0], B[nt], B[4 + nt], bb.x, bb.y);
                    mma_f16     (v[mt][nt], Ah[mt][1], B[8 + nt], B[12 + nt]);
                }
            }
            // sines: nt 0,1 on fma pipe (packed poly), nt 2,3 on MUFU
#pragma unroll
            for (int mt = 0; mt < 2; mt++) {
#pragma unroll
                for (int nt = 0; nt < 2; nt++) {
                    float2 a = sin2_poly(make_float2(v[mt][nt][0], v[mt][nt][1]));
                    float2 b = sin2_poly(make_float2(v[mt][nt][2], v[mt][nt][3]));
                    v[mt][nt][0] = a.x; v[mt][nt][1] = a.y;
                    v[mt][nt][2] = b.x; v[mt][nt][3] = b.y;
                }
#pragma unroll
                for (int nt = 2; nt < 4; nt++)
#pragma unroll
                    for (int i = 0; i < 4; i++)
                        v[mt][nt][i] = __sinf(v[mt][nt][i]);
            }
        }

        // ---- layer 5: 32 -> 16 on HMMA (MUFU sines) ----
        {
            uint32_t Ah[2][2][4];
            BUILD_A(v, Ah);

            uint32_t B5[8];
            {
                const uint4* bp = (const uint4*)&frag5[lane][0];
                uint4 b0_ = bp[0], b1_ = bp[1];
                B5[0]=b0_.x; B5[1]=b0_.y; B5[2]=b0_.z; B5[3]=b0_.w;
                B5[4]=b1_.x; B5[5]=b1_.y; B5[6]=b1_.z; B5[7]=b1_.w;
            }
#pragma unroll
            for (int nt = 0; nt < 2; nt++) {
                float2 bb = bias5[nt * 4 + t4];
#pragma unroll
                for (int mt = 0; mt < 2; mt++) {
                    mma_f16_bias(v[mt][nt], Ah[mt][0], B5[nt], B5[2 + nt], bb.x, bb.y);
                    mma_f16     (v[mt][nt], Ah[mt][1], B5[4 + nt], B5[6 + nt]);
                }
            }
#pragma unroll
            for (int mt = 0; mt < 2; mt++)
#pragma unroll
                for (int nt = 0; nt < 2; nt++)
#pragma unroll
                    for (int i = 0; i < 4; i++)
                        v[mt][nt][i] = __sinf(v[mt][nt][i]);
        }

        // ---- final 16 -> 3 + sigmoid ----
#pragma unroll
        for (int mt = 0; mt < 2; mt++) {
            float s[2][3];
#pragma unroll
            for (int c = 0; c < 3; c++) {
                float2 wa = ((const float2*)s_wf)[c * 8 + t4];
                float2 wb = ((const float2*)s_wf)[c * 8 + 4 + t4];
#pragma unroll
                for (int r = 0; r < 2; r++) {
                    float acc = v[mt][0][2 * r]     * wa.x
                              + v[mt][0][2 * r + 1] * wa.y
                              + v[mt][1][2 * r]     * wb.x
                              + v[mt][1][2 * r + 1] * wb.y;
                    acc += __shfl_xor_sync(0xffffffffu, acc, 1);
                    acc += __shfl_xor_sync(0xffffffffu, acc, 2);
                    s[r][c] = acc + s_bf[c];
                }
            }
            if (t4 < 3) {
#pragma unroll
                for (int r = 0; r < 2; r++) {
                    int p = pbase + mt * 16 + g + 8 * r;
                    if (p < numPts) {
                        float val = (t4 == 0) ? s[r][0] : ((t4 == 1) ? s[r][1] : s[r][2]);
                        out[(size_t)p * 3 + t4] = fast_sigmoid(val);
                    }
                }
            }
        }
    }
}

extern "C" void kernel_launch(void* const* d_in, const int* in_sizes, int n_in,
                              void* d_out, int out_size)
{
    const float* coords = (const float*)d_in[0];
    const float* w0 = (const float*)d_in[1];  const float* b0 = (const float*)d_in[2];
    const float* w1 = (const float*)d_in[3];  const float* b1 = (const float*)d_in[4];
    const float* w2 = (const float*)d_in[5];  const float* b2 = (const float*)d_in[6];
    const float* w3 = (const float*)d_in[7];  const float* b3 = (const float*)d_in[8];
    const float* w4 = (const float*)d_in[9];  const float* b4 = (const float*)d_in[10];
    const float* w5 = (const float*)d_in[11]; const float* b5 = (const float*)d_in[12];
    const float* wf = (const float*)d_in[13]; const float* bf = (const float*)d_in[14];

    int numPts = in_sizes[0] / 2;
    int numTiles = (numPts + 127) / 128;
    int grid = numTiles < MAXCTAS ? numTiles : MAXCTAS;

    siren_hmma<<<grid, BLK>>>(coords, w0, b0, w1, b1, w2, b2, w3, b3, w4, b4,
                              w5, b5, wf, bf, (float*)d_out, numPts, numTiles);
}

// round 12
// speedup vs baseline: 1.0621x; 1.0621x over previous
#include <cuda_runtime.h>
#include <cuda_fp16.h>
#include <cstdint>

#define OMEGA0 30.0f
#define BLK 128
#define MAXCTAS 888   // 148 SMs x 6 CTAs

// ---------------- helpers ----------------
__device__ __forceinline__ float fast_sigmoid(float t) {
    return __fdividef(1.0f, 1.0f + __expf(-t));
}
__device__ __forceinline__ uint32_t pack_f16x2(float x, float y) {
    uint32_t r;
    asm("cvt.rn.f16x2.f32 %0, %1, %2;" : "=r"(r) : "f"(y), "f"(x));
    return r;
}
// D += A * B
__device__ __forceinline__ void mma_f16(float d[4], const uint32_t a[4],
                                        uint32_t b0, uint32_t b1) {
    asm volatile(
        "mma.sync.aligned.m16n8k16.row.col.f32.f16.f16.f32 "
        "{%0,%1,%2,%3}, {%4,%5,%6,%7}, {%8,%9}, {%0,%1,%2,%3};"
        : "+f"(d[0]), "+f"(d[1]), "+f"(d[2]), "+f"(d[3])
        : "r"(a[0]), "r"(a[1]), "r"(a[2]), "r"(a[3]), "r"(b0), "r"(b1));
}
// D = A * B + {c0,c1,c0,c1}
__device__ __forceinline__ void mma_f16_bias(float d[4], const uint32_t a[4],
                                             uint32_t b0, uint32_t b1,
                                             float c0, float c1) {
    asm volatile(
        "mma.sync.aligned.m16n8k16.row.col.f32.f16.f16.f32 "
        "{%0,%1,%2,%3}, {%4,%5,%6,%7}, {%8,%9}, {%10,%11,%10,%11};"
        : "=f"(d[0]), "=f"(d[1]), "=f"(d[2]), "=f"(d[3])
        : "r"(a[0]), "r"(a[1]), "r"(a[2]), "r"(a[3]), "r"(b0), "r"(b1),
          "f"(c0), "f"(c1));
}

// Build A fragments (f16) for k=32 from 4 n-tiles of fp32 values in D layout.
#define BUILD_A(vsrc, Ah) do {                                                  \
    _Pragma("unroll")                                                           \
    for (int mt_ = 0; mt_ < 2; mt_++) {                                         \
        _Pragma("unroll")                                                       \
        for (int kt_ = 0; kt_ < 2; kt_++) {                                     \
            Ah[mt_][kt_][0] = pack_f16x2(vsrc[mt_][2*kt_][0],   vsrc[mt_][2*kt_][1]);   \
            Ah[mt_][kt_][1] = pack_f16x2(vsrc[mt_][2*kt_][2],   vsrc[mt_][2*kt_][3]);   \
            Ah[mt_][kt_][2] = pack_f16x2(vsrc[mt_][2*kt_+1][0], vsrc[mt_][2*kt_+1][1]); \
            Ah[mt_][kt_][3] = pack_f16x2(vsrc[mt_][2*kt_+1][2], vsrc[mt_][2*kt_+1][3]); \
        }                                                                       \
    }                                                                           \
} while (0)

__global__ void __launch_bounds__(BLK, 6)
siren_hmma(const float* __restrict__ coords,
           const float* __restrict__ w0g, const float* __restrict__ b0g,
           const float* __restrict__ w1g, const float* __restrict__ b1g,
           const float* __restrict__ w2g, const float* __restrict__ b2g,
           const float* __restrict__ w3g, const float* __restrict__ b3g,
           const float* __restrict__ w4g, const float* __restrict__ b4g,
           const float* __restrict__ w5g, const float* __restrict__ b5g,
           const float* __restrict__ wfg, const float* __restrict__ bfg,
           float* __restrict__ out, int numPts, int numTiles)
{
    __shared__ __align__(16) uint32_t fragMid[4][32][20];
    __shared__ __align__(16) uint32_t frag5[32][12];
    __shared__ __align__(16) uint32_t fragL0[32][12];   // q 0..7 used, 12-stride conflict-free
    __shared__ __align__(8)  uint32_t fragF[32][2];
    __shared__ float2 biasM[4][16];
    __shared__ float2 bias5[8];
    __shared__ float2 biasF[4];

    const int tid = threadIdx.x;
    const int lane = tid & 31, wid = tid >> 5;
    const int t4 = lane & 3, g = lane >> 2;

    // ---- fill mid-layer weight fragments ----
#define FILL_MID(Lc, WP)                                                       \
    for (int e = tid; e < 512; e += BLK) {                                     \
        int q = e >> 5, ln = e & 31;                                           \
        int tt = ln & 3, gg = ln >> 2;                                         \
        int kt = q >> 3, r = (q >> 2) & 1, nt = q & 3;                         \
        int k0 = kt * 16 + r * 8 + tt * 2;                                     \
        int n  = nt * 8 + gg;                                                  \
        fragMid[Lc][ln][q] = pack_f16x2(OMEGA0 * WP[n * 32 + k0],              \
                                        OMEGA0 * WP[n * 32 + k0 + 1]);         \
    }
    FILL_MID(0, w1g) FILL_MID(1, w2g) FILL_MID(2, w3g) FILL_MID(3, w4g)
#undef FILL_MID

    // ---- layer-5 fragments ----
    for (int e = tid; e < 256; e += BLK) {
        int q = e >> 5, ln = e & 31;
        int tt = ln & 3, gg = ln >> 2;
        int kt = q >> 2, r = (q >> 1) & 1, nt = q & 1;
        int k0 = kt * 16 + r * 8 + tt * 2;
        int n  = nt * 8 + gg;
        frag5[ln][q] = pack_f16x2(OMEGA0 * w5g[n * 32 + k0],
                                  OMEGA0 * w5g[n * 32 + k0 + 1]);
    }

    // ---- layer-0 fragments: k0,1=W_hi; k2,3=W_hi(x_lo); k4=b_hi,k5=b_lo; k8,9=W_lo ----
    for (int e = tid; e < 256; e += BLK) {
        int q = e >> 5, ln = e & 31;       // q 0..7 = r*4 + nt
        int tt = ln & 3, gg = ln >> 2;
        int r = q >> 2, nt = q & 3;
        int n = nt * 8 + gg;
        float w0v = OMEGA0 * w0g[n * 2];
        float w1v = OMEGA0 * w0g[n * 2 + 1];
        __half2 wh2 = __floats2half2_rn(w0v, w1v);
        float2 whf = __half22float2(wh2);
        uint32_t val = 0;
        if (r == 0) {
            if (tt == 0 || tt == 1) {
                val = *reinterpret_cast<uint32_t*>(&wh2);     // W_hi (x_hi and x_lo slots)
            } else if (tt == 2) {
                float bv = OMEGA0 * b0g[n];
                float bhf = __half2float(__float2half_rn(bv));
                val = pack_f16x2(bv, bv - bhf);               // (b_hi, b_lo)
            }
        } else {
            if (tt == 0) val = pack_f16x2(w0v - whf.x, w1v - whf.y);  // W_lo
        }
        fragL0[ln][q] = val;
    }

    // ---- final-layer fragments (n=8, cols 0..2 live) ----
    if (tid < 32) {
        int tt = tid & 3, gg = tid >> 2;
        uint32_t b0v = 0, b1v = 0;
        if (gg < 3) {
            b0v = pack_f16x2(wfg[gg * 16 + 2 * tt],     wfg[gg * 16 + 2 * tt + 1]);
            b1v = pack_f16x2(wfg[gg * 16 + 8 + 2 * tt], wfg[gg * 16 + 8 + 2 * tt + 1]);
        }
        fragF[tid][0] = b0v;
        fragF[tid][1] = b1v;
    }
    if (tid < 4) {
        float c0 = (2 * tid     < 3) ? bfg[2 * tid]     : 0.0f;
        float c1 = (2 * tid + 1 < 3) ? bfg[2 * tid + 1] : 0.0f;
        biasF[tid] = make_float2(c0, c1);
    }
#define FILL_BIAS(Lc, BP)                                                      \
    if (tid < 16) {                                                            \
        int nt = tid >> 2, tt = tid & 3;                                       \
        biasM[Lc][tid] = make_float2(OMEGA0 * BP[nt * 8 + tt * 2],             \
                                     OMEGA0 * BP[nt * 8 + tt * 2 + 1]);        \
    }
    FILL_BIAS(0, b1g) FILL_BIAS(1, b2g) FILL_BIAS(2, b3g) FILL_BIAS(3, b4g)
#undef FILL_BIAS
    if (tid < 8) {
        int nt = tid >> 2, tt = tid & 3;
        bias5[tid] = make_float2(OMEGA0 * b5g[nt * 8 + tt * 2],
                                 OMEGA0 * b5g[nt * 8 + tt * 2 + 1]);
    }
    __syncthreads();

    const uint32_t ONE2 = 0x3C003C00u;  // f16x2 (1.0, 1.0)

    // ---------------- main loop: 128 points per CTA-iter (32 per warp) ----------------
#pragma unroll 1
    for (int tile = blockIdx.x; tile < numTiles; tile += gridDim.x) {
        const int pbase = tile * 128 + wid * 32;

        float v[2][4][4];

        // ---- layer 0: 2 -> 32 on HMMA (hi/lo exact) ----
        {
            uint32_t BL0[8];
            {
                const uint4* bp = (const uint4*)&fragL0[lane][0];
                uint4 x0 = bp[0], x1 = bp[1];
                BL0[0]=x0.x; BL0[1]=x0.y; BL0[2]=x0.z; BL0[3]=x0.w;
                BL0[4]=x1.x; BL0[5]=x1.y; BL0[6]=x1.z; BL0[7]=x1.w;
            }
#pragma unroll
            for (int mt = 0; mt < 2; mt++) {
                int p0 = pbase + mt * 16 + g;
                float2 c0 = (p0 < numPts)     ? ((const float2*)coords)[p0]     : make_float2(0.f, 0.f);
                float2 c1 = (p0 + 8 < numPts) ? ((const float2*)coords)[p0 + 8] : make_float2(0.f, 0.f);
                __half2 h0 = __floats2half2_rn(c0.x, c0.y);
                __half2 h1 = __floats2half2_rn(c1.x, c1.y);
                float2 h0f = __half22float2(h0);
                float2 h1f = __half22float2(h1);
                uint32_t hi0 = *reinterpret_cast<uint32_t*>(&h0);
                uint32_t hi1 = *reinterpret_cast<uint32_t*>(&h1);
                uint32_t lo0 = pack_f16x2(c0.x - h0f.x, c0.y - h0f.y);
                uint32_t lo1 = pack_f16x2(c1.x - h1f.x, c1.y - h1f.y);

                uint32_t A[4];
                A[0] = (t4 == 0) ? hi0 : (t4 == 1) ? lo0 : (t4 == 2) ? ONE2 : 0u;
                A[1] = (t4 == 0) ? hi1 : (t4 == 1) ? lo1 : (t4 == 2) ? ONE2 : 0u;
                A[2] = (t4 == 0) ? hi0 : 0u;
                A[3] = (t4 == 0) ? hi1 : 0u;
#pragma unroll
                for (int nt = 0; nt < 4; nt++)
                    mma_f16_bias(v[mt][nt], A, BL0[nt], BL0[4 + nt], 0.0f, 0.0f);
            }
#pragma unroll
            for (int mt = 0; mt < 2; mt++)
#pragma unroll
                for (int nt = 0; nt < 4; nt++)
#pragma unroll
                    for (int i = 0; i < 4; i++)
                        v[mt][nt][i] = __sinf(v[mt][nt][i]);
        }

        // ---- 4 middle layers 32 -> 32 on HMMA ----
#pragma unroll 1
        for (int L = 0; L < 4; L++) {
            uint32_t Ah[2][2][4];
            BUILD_A(v, Ah);

            uint32_t B[16];
            {
                const uint4* bp = (const uint4*)&fragMid[L][lane][0];
                uint4 b0_ = bp[0], b1_ = bp[1], b2_ = bp[2], b3_ = bp[3];
                B[0]=b0_.x; B[1]=b0_.y; B[2]=b0_.z; B[3]=b0_.w;
                B[4]=b1_.x; B[5]=b1_.y; B[6]=b1_.z; B[7]=b1_.w;
                B[8]=b2_.x; B[9]=b2_.y; B[10]=b2_.z; B[11]=b2_.w;
                B[12]=b3_.x; B[13]=b3_.y; B[14]=b3_.z; B[15]=b3_.w;
            }
#pragma unroll
            for (int nt = 0; nt < 4; nt++) {
                float2 bb = biasM[L][nt * 4 + t4];
#pragma unroll
                for (int mt = 0; mt < 2; mt++) {
                    mma_f16_bias(v[mt][nt], Ah[mt][0], B[nt], B[4 + nt], bb.x, bb.y);
                    mma_f16     (v[mt][nt], Ah[mt][1], B[8 + nt], B[12 + nt]);
                }
            }
#pragma unroll
            for (int mt = 0; mt < 2; mt++)
#pragma unroll
                for (int nt = 0; nt < 4; nt++)
#pragma unroll
                    for (int i = 0; i < 4; i++)
                        v[mt][nt][i] = __sinf(v[mt][nt][i]);
        }

        // ---- layer 5: 32 -> 16 on HMMA ----
        {
            uint32_t Ah[2][2][4];
            BUILD_A(v, Ah);

            uint32_t B5[8];
            {
                const uint4* bp = (const uint4*)&frag5[lane][0];
                uint4 b0_ = bp[0], b1_ = bp[1];
                B5[0]=b0_.x; B5[1]=b0_.y; B5[2]=b0_.z; B5[3]=b0_.w;
                B5[4]=b1_.x; B5[5]=b1_.y; B5[6]=b1_.z; B5[7]=b1_.w;
            }
#pragma unroll
            for (int nt = 0; nt < 2; nt++) {
                float2 bb = bias5[nt * 4 + t4];
#pragma unroll
                for (int mt = 0; mt < 2; mt++) {
                    mma_f16_bias(v[mt][nt], Ah[mt][0], B5[nt], B5[2 + nt], bb.x, bb.y);
                    mma_f16     (v[mt][nt], Ah[mt][1], B5[4 + nt], B5[6 + nt]);
                }
            }
#pragma unroll
            for (int mt = 0; mt < 2; mt++)
#pragma unroll
                for (int nt = 0; nt < 2; nt++)
#pragma unroll
                    for (int i = 0; i < 4; i++)
                        v[mt][nt][i] = __sinf(v[mt][nt][i]);
        }

        // ---- final layer 16 -> 3 on HMMA + sigmoid + predicated stores ----
        {
            uint32_t Bf0 = fragF[lane][0];
            uint32_t Bf1 = fragF[lane][1];
            float2 cb = biasF[t4];
#pragma unroll
            for (int mt = 0; mt < 2; mt++) {
                uint32_t A[4];
                A[0] = pack_f16x2(v[mt][0][0], v[mt][0][1]);
                A[1] = pack_f16x2(v[mt][0][2], v[mt][0][3]);
                A[2] = pack_f16x2(v[mt][1][0], v[mt][1][1]);
                A[3] = pack_f16x2(v[mt][1][2], v[mt][1][3]);
                float d[4];
                mma_f16_bias(d, A, Bf0, Bf1, cb.x, cb.y);

                int p0 = pbase + mt * 16 + g;
                int p1 = p0 + 8;
                if (t4 == 0) {
                    if (p0 < numPts) {
                        out[(size_t)p0 * 3 + 0] = fast_sigmoid(d[0]);
                        out[(size_t)p0 * 3 + 1] = fast_sigmoid(d[1]);
                    }
                    if (p1 < numPts) {
                        out[(size_t)p1 * 3 + 0] = fast_sigmoid(d[2]);
                        out[(size_t)p1 * 3 + 1] = fast_sigmoid(d[3]);
                    }
                } else if (t4 == 1) {
                    if (p0 < numPts) out[(size_t)p0 * 3 + 2] = fast_sigmoid(d[0]);
                    if (p1 < numPts) out[(size_t)p1 * 3 + 2] = fast_sigmoid(d[2]);
                }
            }
        }
    }
}

extern "C" void kernel_launch(void* const* d_in, const int* in_sizes, int n_in,
                              void* d_out, int out_size)
{
    const float* coords = (const float*)d_in[0];
    const float* w0 = (const float*)d_in[1];  const float* b0 = (const float*)d_in[2];
    const float* w1 = (const float*)d_in[3];  const float* b1 = (const float*)d_in[4];
    const float* w2 = (const float*)d_in[5];  const float* b2 = (const float*)d_in[6];
    const float* w3 = (const float*)d_in[7];  const float* b3 = (const float*)d_in[8];
    const float* w4 = (const float*)d_in[9];  const float* b4 = (const float*)d_in[10];
    const float* w5 = (const float*)d_in[11]; const float* b5 = (const float*)d_in[12];
    const float* wf = (const float*)d_in[13]; const float* bf = (const float*)d_in[14];

    int numPts = in_sizes[0] / 2;
    int numTiles = (numPts + 127) / 128;
    int grid = numTiles < MAXCTAS ? numTiles : MAXCTAS;

    siren_hmma<<<grid, BLK>>>(coords, w0, b0, w1, b1, w2, b2, w3, b3, w4, b4,
                              w5, b5, wf, bf, (float*)d_out, numPts, numTiles);
}

// round 13
// speedup vs baseline: 1.1371x; 1.0705x over previous
#include <cuda_runtime.h>
#include <cuda_fp16.h>
#include <cstdint>

#define OMEGA0 30.0f
#define BLK 128
#define MAXCTAS 1036   // 148 SMs x 7 CTAs

// ---------------- helpers ----------------
__device__ __forceinline__ float fast_sigmoid(float t) {
    return __fdividef(1.0f, 1.0f + __expf(-t));
}
__device__ __forceinline__ uint32_t pack_f16x2(float x, float y) {
    uint32_t r;
    asm("cvt.rn.f16x2.f32 %0, %1, %2;" : "=r"(r) : "f"(y), "f"(x));
    return r;
}
// D += A * B
__device__ __forceinline__ void mma_f16(float d[4], const uint32_t a[4],
                                        uint32_t b0, uint32_t b1) {
    asm volatile(
        "mma.sync.aligned.m16n8k16.row.col.f32.f16.f16.f32 "
        "{%0,%1,%2,%3}, {%4,%5,%6,%7}, {%8,%9}, {%0,%1,%2,%3};"
        : "+f"(d[0]), "+f"(d[1]), "+f"(d[2]), "+f"(d[3])
        : "r"(a[0]), "r"(a[1]), "r"(a[2]), "r"(a[3]), "r"(b0), "r"(b1));
}
// D = A * B + {c0,c1,c0,c1}
__device__ __forceinline__ void mma_f16_bias(float d[4], const uint32_t a[4],
                                             uint32_t b0, uint32_t b1,
                                             float c0, float c1) {
    asm volatile(
        "mma.sync.aligned.m16n8k16.row.col.f32.f16.f16.f32 "
        "{%0,%1,%2,%3}, {%4,%5,%6,%7}, {%8,%9}, {%10,%11,%10,%11};"
        : "=f"(d[0]), "=f"(d[1]), "=f"(d[2]), "=f"(d[3])
        : "r"(a[0]), "r"(a[1]), "r"(a[2]), "r"(a[3]), "r"(b0), "r"(b1),
          "f"(c0), "f"(c1));
}

// one mid layer: Ain (A fragments) -> Aout (A fragments), sines fused with pack
#define MID_LAYER(Ain, Aout, Lc) do {                                          \
    uint32_t B_[16];                                                           \
    {                                                                          \
        const uint4* bp_ = (const uint4*)&fragMid[Lc][lane][0];                \
        uint4 q0_ = bp_[0], q1_ = bp_[1], q2_ = bp_[2], q3_ = bp_[3];          \
        B_[0]=q0_.x; B_[1]=q0_.y; B_[2]=q0_.z; B_[3]=q0_.w;                    \
        B_[4]=q1_.x; B_[5]=q1_.y; B_[6]=q1_.z; B_[7]=q1_.w;                    \
        B_[8]=q2_.x; B_[9]=q2_.y; B_[10]=q2_.z; B_[11]=q2_.w;                  \
        B_[12]=q3_.x; B_[13]=q3_.y; B_[14]=q3_.z; B_[15]=q3_.w;                \
    }                                                                          \
    _Pragma("unroll")                                                          \
    for (int nt_ = 0; nt_ < 4; nt_++) {                                        \
        float2 bb_ = biasM[Lc][nt_ * 4 + t4];                                  \
        _Pragma("unroll")                                                      \
        for (int mt_ = 0; mt_ < 2; mt_++) {                                    \
            float d_[4];                                                       \
            mma_f16_bias(d_, Ain[mt_][0], B_[nt_], B_[4 + nt_], bb_.x, bb_.y); \
            mma_f16     (d_, Ain[mt_][1], B_[8 + nt_], B_[12 + nt_]);          \
            d_[0] = __sinf(d_[0]); d_[1] = __sinf(d_[1]);                      \
            d_[2] = __sinf(d_[2]); d_[3] = __sinf(d_[3]);                      \
            Aout[mt_][nt_ >> 1][2 * (nt_ & 1)]     = pack_f16x2(d_[0], d_[1]); \
            Aout[mt_][nt_ >> 1][2 * (nt_ & 1) + 1] = pack_f16x2(d_[2], d_[3]); \
        }                                                                      \
    }                                                                          \
} while (0)

__global__ void __launch_bounds__(BLK, 7)
siren_hmma(const float* __restrict__ coords,
           const float* __restrict__ w0g, const float* __restrict__ b0g,
           const float* __restrict__ w1g, const float* __restrict__ b1g,
           const float* __restrict__ w2g, const float* __restrict__ b2g,
           const float* __restrict__ w3g, const float* __restrict__ b3g,
           const float* __restrict__ w4g, const float* __restrict__ b4g,
           const float* __restrict__ w5g, const float* __restrict__ b5g,
           const float* __restrict__ wfg, const float* __restrict__ bfg,
           float* __restrict__ out, int numPts, int numTiles)
{
    __shared__ __align__(16) uint32_t fragMid[4][32][20];
    __shared__ __align__(16) uint32_t frag5[32][12];
    __shared__ float2 biasM[4][16];
    __shared__ float2 bias5[8];
    __shared__ float s_w0[64], s_b0[32], s_wf[48], s_bf[3];

    const int tid = threadIdx.x;
    const int lane = tid & 31, wid = tid >> 5;
    const int t4 = lane & 3, g = lane >> 2;

    // ---- fill weight fragments ----
#define FILL_MID(Lc, WP)                                                       \
    for (int e = tid; e < 512; e += BLK) {                                     \
        int q = e >> 5, ln = e & 31;                                           \
        int tt = ln & 3, gg = ln >> 2;                                         \
        int kt = q >> 3, r = (q >> 2) & 1, nt = q & 3;                         \
        int k0 = kt * 16 + r * 8 + tt * 2;                                     \
        int n  = nt * 8 + gg;                                                  \
        fragMid[Lc][ln][q] = pack_f16x2(OMEGA0 * WP[n * 32 + k0],              \
                                        OMEGA0 * WP[n * 32 + k0 + 1]);         \
    }
    FILL_MID(0, w1g) FILL_MID(1, w2g) FILL_MID(2, w3g) FILL_MID(3, w4g)
#undef FILL_MID

    for (int e = tid; e < 256; e += BLK) {
        int q = e >> 5, ln = e & 31;
        int tt = ln & 3, gg = ln >> 2;
        int kt = q >> 2, r = (q >> 1) & 1, nt = q & 1;
        int k0 = kt * 16 + r * 8 + tt * 2;
        int n  = nt * 8 + gg;
        frag5[ln][q] = pack_f16x2(OMEGA0 * w5g[n * 32 + k0],
                                  OMEGA0 * w5g[n * 32 + k0 + 1]);
    }
#define FILL_BIAS(Lc, BP)                                                      \
    if (tid < 16) {                                                            \
        int nt = tid >> 2, tt = tid & 3;                                       \
        biasM[Lc][tid] = make_float2(OMEGA0 * BP[nt * 8 + tt * 2],             \
                                     OMEGA0 * BP[nt * 8 + tt * 2 + 1]);        \
    }
    FILL_BIAS(0, b1g) FILL_BIAS(1, b2g) FILL_BIAS(2, b3g) FILL_BIAS(3, b4g)
#undef FILL_BIAS
    if (tid < 8) {
        int nt = tid >> 2, tt = tid & 3;
        bias5[tid] = make_float2(OMEGA0 * b5g[nt * 8 + tt * 2],
                                 OMEGA0 * b5g[nt * 8 + tt * 2 + 1]);
    }
    if (tid < 64) s_w0[tid] = OMEGA0 * w0g[tid];
    if (tid < 32) s_b0[tid] = OMEGA0 * b0g[tid];
    if (tid < 48) s_wf[tid] = wfg[tid];
    if (tid < 3)  s_bf[tid] = bfg[tid];
    __syncthreads();

    // ---------------- main loop: 128 points per CTA-iter (32 per warp) ----------------
#pragma unroll 1
    for (int tile = blockIdx.x; tile < numTiles; tile += gridDim.x) {
        const int pbase = tile * 128 + wid * 32;

        uint32_t A0[2][2][4], A1[2][2][4];   // activations as packed A-fragments

        // ---- layer 0: 2 -> 32 scalar, packed directly into A0 ----
#pragma unroll
        for (int mt = 0; mt < 2; mt++) {
            int p0 = pbase + mt * 16 + g;
            float2 c0 = (p0 < numPts)     ? ((const float2*)coords)[p0]     : make_float2(0.f, 0.f);
            float2 c1 = (p0 + 8 < numPts) ? ((const float2*)coords)[p0 + 8] : make_float2(0.f, 0.f);
#pragma unroll
            for (int nt = 0; nt < 4; nt++) {
                int col = nt * 8 + t4 * 2;
                float2 wa = ((const float2*)s_w0)[col];
                float2 wb = ((const float2*)s_w0)[col + 1];
                float ba = s_b0[col], bb_ = s_b0[col + 1];
                float d0 = __sinf(fmaf(c0.x, wa.x, fmaf(c0.y, wa.y, ba)));
                float d1 = __sinf(fmaf(c0.x, wb.x, fmaf(c0.y, wb.y, bb_)));
                float d2 = __sinf(fmaf(c1.x, wa.x, fmaf(c1.y, wa.y, ba)));
                float d3 = __sinf(fmaf(c1.x, wb.x, fmaf(c1.y, wb.y, bb_)));
                A0[mt][nt >> 1][2 * (nt & 1)]     = pack_f16x2(d0, d1);
                A0[mt][nt >> 1][2 * (nt & 1) + 1] = pack_f16x2(d2, d3);
            }
        }

        // ---- 4 middle layers, ping-pong fragment arrays ----
        MID_LAYER(A0, A1, 0);
        MID_LAYER(A1, A0, 1);
        MID_LAYER(A0, A1, 2);
        MID_LAYER(A1, A0, 3);

        // ---- layer 5: 32 -> 16, output kept as f32 z ----
        float z[2][2][4];
        {
            uint32_t B5[8];
            {
                const uint4* bp = (const uint4*)&frag5[lane][0];
                uint4 b0_ = bp[0], b1_ = bp[1];
                B5[0]=b0_.x; B5[1]=b0_.y; B5[2]=b0_.z; B5[3]=b0_.w;
                B5[4]=b1_.x; B5[5]=b1_.y; B5[6]=b1_.z; B5[7]=b1_.w;
            }
#pragma unroll
            for (int nt = 0; nt < 2; nt++) {
                float2 bb = bias5[nt * 4 + t4];
#pragma unroll
                for (int mt = 0; mt < 2; mt++) {
                    mma_f16_bias(z[mt][nt], A0[mt][0], B5[nt], B5[2 + nt], bb.x, bb.y);
                    mma_f16     (z[mt][nt], A0[mt][1], B5[4 + nt], B5[6 + nt]);
#pragma unroll
                    for (int i = 0; i < 4; i++)
                        z[mt][nt][i] = __sinf(z[mt][nt][i]);
                }
            }
        }

        // ---- final 16 -> 3 + sigmoid: per-lane partials + butterfly reduce ----
#pragma unroll
        for (int mt = 0; mt < 2; mt++) {
            float s[2][3];
#pragma unroll
            for (int c = 0; c < 3; c++) {
                float2 wa = ((const float2*)s_wf)[c * 8 + t4];
                float2 wb = ((const float2*)s_wf)[c * 8 + 4 + t4];
#pragma unroll
                for (int r = 0; r < 2; r++) {
                    float acc = z[mt][0][2 * r]     * wa.x
                              + z[mt][0][2 * r + 1] * wa.y
                              + z[mt][1][2 * r]     * wb.x
                              + z[mt][1][2 * r + 1] * wb.y;
                    acc += __shfl_xor_sync(0xffffffffu, acc, 1);
                    acc += __shfl_xor_sync(0xffffffffu, acc, 2);
                    s[r][c] = acc + s_bf[c];
                }
            }
            if (t4 < 3) {
#pragma unroll
                for (int r = 0; r < 2; r++) {
                    int p = pbase + mt * 16 + g + 8 * r;
                    if (p < numPts) {
                        float val = (t4 == 0) ? s[r][0] : ((t4 == 1) ? s[r][1] : s[r][2]);
                        out[(size_t)p * 3 + t4] = fast_sigmoid(val);
                    }
                }
            }
        }
    }
}

extern "C" void kernel_launch(void* const* d_in, const int* in_sizes, int n_in,
                              void* d_out, int out_size)
{
    const float* coords = (const float*)d_in[0];
    const float* w0 = (const float*)d_in[1];  const float* b0 = (const float*)d_in[2];
    const float* w1 = (const float*)d_in[3];  const float* b1 = (const float*)d_in[4];
    const float* w2 = (const float*)d_in[5];  const float* b2 = (const float*)d_in[6];
    const float* w3 = (const float*)d_in[7];  const float* b3 = (const float*)d_in[8];
    const float* w4 = (const float*)d_in[9];  const float* b4 = (const float*)d_in[10];
    const float* w5 = (const float*)d_in[11]; const float* b5 = (const float*)d_in[12];
    const float* wf = (const float*)d_in[13]; const float* bf = (const float*)d_in[14];

    int numPts = in_sizes[0] / 2;
    int numTiles = (numPts + 127) / 128;
    int grid = numTiles < MAXCTAS ? numTiles : MAXCTAS;

    siren_hmma<<<grid, BLK>>>(coords, w0, b0, w1, b1, w2, b2, w3, b3, w4, b4,
                              w5, b5, wf, bf, (float*)d_out, numPts, numTiles);
}